// round 16
// baseline (speedup 1.0000x reference)
#include <cuda_runtime.h>
#include <cstdint>

// ---------------------------------------------------------------------------
// LSTM Neural Hawkes Process NLL  (B=64, L=1024, H=64)
// R16: rebalanced coarsening. Block = 256 threads.
//  Scan CTA:
//    threads 0-191  : producers, TWO columns each (c0=j gates 0-2,
//                     c1=j+192 gates 3-5 -> c1 constants warp-uniform)
//    threads 192-255: epilogue, ONE column each (gate-6 of channel ch) ->
//                     pacer cycle loses a whole col_dot vs R15.
//  Fabric unchanged: bar1(256) arrive/sync, bar2(256) sync/arrive, bar3(64),
//  post-release STG, chunked g_flag publish; consumer CTA = 8 warps.
// ---------------------------------------------------------------------------

#define BATCH   64
#define MAXL    1024
#define LP1     1025
#define HID     64
#define NCOL    448
#define NTHR    256
#define NPROD   192
#define NMC     30
#define T_END   100.0f
#define EPS_L   1e-10f
#define TOTAL   (BATCH * LP1)          // 65600
#define LOG2E   1.4426950408889634f
#define LN2     0.6931471805599453f

// ------------------------- device scratch (no mallocs) ---------------------
__device__ float4   g_state[TOTAL * HID];  // {c, cbar, o, dec}
__device__ unsigned g_flag [BATCH];
__device__ float    g_part [BATCH];
__device__ unsigned g_done = 0;

// ------------------------------ fast math -----------------------------------
__device__ __forceinline__ float ex2f(float x){ float y; asm("ex2.approx.f32 %0,%1;":"=f"(y):"f"(x)); return y; }
__device__ __forceinline__ float lg2f(float x){ float y; asm("lg2.approx.f32 %0,%1;":"=f"(y):"f"(x)); return y; }
__device__ __forceinline__ float tanh_mufu(float x){ float y; asm("tanh.approx.f32 %0,%1;":"=f"(y):"f"(x)); return y; }
__device__ __forceinline__ float fsoftplus(float x){
    return fmaxf(x, 0.0f) + LN2 * lg2f(1.0f + ex2f(-fabsf(x) * LOG2E));
}
__device__ __forceinline__ float flog(float x){ return LN2 * lg2f(x); }

// ------------------------------ packed f32x2 --------------------------------
__device__ __forceinline__ void fma2(unsigned long long& d, unsigned long long a, unsigned long long b){
    asm("fma.rn.f32x2 %0, %1, %2, %0;" : "+l"(d) : "l"(a), "l"(b));
}
__device__ __forceinline__ void add2(unsigned long long& d, unsigned long long a){
    asm("add.rn.f32x2 %0, %1, %0;" : "+l"(d) : "l"(a));
}
__device__ __forceinline__ unsigned long long pack2(float lo, float hi){
    unsigned long long r; asm("mov.b64 %0, {%1,%2};" : "=l"(r) : "f"(lo), "f"(hi)); return r;
}
__device__ __forceinline__ float2 unpack2(unsigned long long v){
    float2 r; asm("mov.b64 {%0,%1}, %2;" : "=f"(r.x), "=f"(r.y) : "l"(v)); return r;
}

// --------------------------- publish primitives ------------------------------
__device__ __forceinline__ void st_release_u32(unsigned* p, unsigned v){
    asm volatile("st.release.gpu.global.u32 [%0], %1;" :: "l"(p), "r"(v) : "memory");
}
__device__ __forceinline__ unsigned ld_acquire_u32(const unsigned* p){
    unsigned v;
    asm volatile("ld.acquire.gpu.global.u32 %0, [%1];" : "=r"(v) : "l"(p) : "memory");
    return v;
}

// ------------------------------ named barriers ------------------------------
#define BAR1_ARRIVE() asm volatile("bar.arrive 1, 256;" ::: "memory")
#define BAR1_SYNC()   asm volatile("bar.sync   1, 256;" ::: "memory")
#define BAR2_ARRIVE() asm volatile("bar.arrive 2, 256;" ::: "memory")
#define BAR2_SYNC()   asm volatile("bar.sync   2, 256;" ::: "memory")
#define BAR3_SYNC()   asm volatile("bar.sync   3, 64;"  ::: "memory")

// ------------------------------ Threefry-2x32-20 ----------------------------
__device__ __forceinline__ uint32_t rotl32(uint32_t x, int r){ return (x << r) | (x >> (32 - r)); }
__device__ __forceinline__ float tf_uniform(uint32_t flat){
    // JAX partitionable threefry, key (0,42): bits = out0 ^ out1
    uint32_t k0 = 0u, k1 = 42u, ks2 = k0 ^ k1 ^ 0x1BD11BDAu;
    uint32_t x0 = 0u + k0, x1 = flat + k1;
#define TF_R(r) { x0 += x1; x1 = rotl32(x1, (r)); x1 ^= x0; }
    TF_R(13) TF_R(15) TF_R(26) TF_R(6)   x0 += k1;  x1 += ks2 + 1u;
    TF_R(17) TF_R(29) TF_R(16) TF_R(24)  x0 += ks2; x1 += k0  + 2u;
    TF_R(13) TF_R(15) TF_R(26) TF_R(6)   x0 += k0;  x1 += k1  + 3u;
    TF_R(17) TF_R(29) TF_R(16) TF_R(24)  x0 += k1;  x1 += ks2 + 4u;
    TF_R(13) TF_R(15) TF_R(26) TF_R(6)   x0 += ks2; x1 += k0  + 5u;
#undef TF_R
    uint32_t bits = x0 ^ x1;
    return __uint_as_float((bits >> 9) | 0x3F800000u) - 1.0f;
}

// 64-term packed-f32x2 column dot (2 accumulators)
__device__ __forceinline__ float col_dot(const float* sh, const unsigned long long* w2,
                                         float base)
{
    unsigned long long a0 = 0ull, a1 = 0ull;
    const ulonglong2* h2 = reinterpret_cast<const ulonglong2*>(sh);
#pragma unroll
    for (int q = 0; q < 8; q++) {
        ulonglong2 u = h2[q], v = h2[q + 8];
        fma2(a0, w2[2*q],      u.x);
        fma2(a1, w2[2*q + 1],  u.y);
        fma2(a0, w2[2*q + 16], v.x);
        fma2(a1, w2[2*q + 17], v.y);
    }
    add2(a0, a1);
    float2 r = unpack2(a0);
    return (r.x + r.y) + base;
}

// --------------------------- shared memory union -----------------------------
union SmemU {
    struct {
        float h[HID];
        float v[384];
        float dt[LP1];
    } scan;
    struct {
        float4 stg[8][HID];
        float  red[8];
    } mc;
};

// ------------------------------- main kernel ---------------------------------
__global__ void __launch_bounds__(NTHR, 1)
hawkes_kernel(const float* __restrict__ seq,    // [B, L, 1]
              const float* __restrict__ Wrec,   // [65, 448]
              const float* __restrict__ brec,   // [448]
              const float* __restrict__ Wf,     // [64]
              const float* __restrict__ bf,     // [1]
              const int*   __restrict__ lens,   // [B]
              float*       __restrict__ out)
{
    __shared__ SmemU smem;

    const int j    = threadIdx.x;
    const int w    = j >> 5;
    const int lane = j & 31;

    if (blockIdx.x < BATCH) {
        // ========================= SCAN role ===============================
        const int b   = blockIdx.x;
        const int len = lens[b];
        const float* sp = seq + b * MAXL;
        float* s_h  = smem.scan.h;
        float* s_v  = smem.scan.v;
        float* s_dt = smem.scan.dt;

        for (int l = j; l <= MAXL; l += NTHR) {
            float v;
            if (l < len)        v = (l == 0) ? sp[0] : sp[l] - sp[l - 1];
            else if (l == len)  v = T_END - sp[len - 1];
            else                v = -1.0f;
            s_dt[l] = v;
        }

        const bool epi = (j >= NPROD);

        if (!epi) {
            // ------------- producers: threads 0-191, two columns -----------
            const int c0 = j;               // gates 0..2
            const int c1 = j + NPROD;       // gates 3..5 (always sigmoid)
            const float w00 = Wrec[c0], bj0 = brec[c0];
            const float w01 = Wrec[c1], bj1 = brec[c1];
            unsigned long long w2a[32], w2b[32];
#pragma unroll
            for (int k = 0; k < 32; k++) {
                w2a[k] = pack2(Wrec[(2*k + 1) * NCOL + c0], Wrec[(2*k + 2) * NCOL + c0]);
                w2b[k] = pack2(Wrec[(2*k + 1) * NCOL + c1], Wrec[(2*k + 2) * NCOL + c1]);
            }
            const int g0 = c0 >> 6;         // 0,1,2
            const float al0 = (g0 == 2) ? 1.0f : 0.5f, be0 = al0;
            const float ga0 = (g0 == 2) ? 0.0f : 0.5f;

            __syncthreads();

            for (int l = 0; l < len; l++) {
                const float dt = s_dt[l];
                const float acc0 = col_dot(s_h, w2a, fmaf(w00, dt, bj0));
                const float acc1 = col_dot(s_h, w2b, fmaf(w01, dt, bj1));
                s_v[c0] = fmaf(al0, tanh_mufu(be0 * acc0), ga0);
                s_v[c1] = fmaf(0.5f, tanh_mufu(0.5f * acc1), 0.5f);
                BAR1_ARRIVE();
                BAR2_SYNC();            // h(l+1) ready
            }
        } else {
            // -------- epilogue: threads 192-255, ONE gate-6 column ---------
            const int ch = j - NPROD;       // channel
            const int c1 = 384 + ch;        // gate-6 column
            const float w01 = Wrec[c1], bj1 = brec[c1];
            unsigned long long w2b[32];
#pragma unroll
            for (int k = 0; k < 32; k++)
                w2b[k] = pack2(Wrec[(2*k + 1) * NCOL + c1], Wrec[(2*k + 2) * NCOL + c1]);

            s_h[ch] = 0.0f;
            g_state[(b * LP1) * HID + ch] = make_float4(0.f, 0.f, 0.f, 0.f);

            __syncthreads();

            float ct = 0.0f, cbar = 0.0f;
            for (int l = 0; l < len; l++) {
                const float acc1 = col_dot(s_h, w2b, fmaf(w01, s_dt[l], bj1));
                const float dec = fsoftplus(acc1);
                const float e   = ex2f(-dec * s_dt[l + 1] * LOG2E);

                BAR1_SYNC();            // gates ready
                const float iG = s_v[ch],        fG = s_v[ 64 + ch];
                const float zG = s_v[128 + ch],  oG = s_v[192 + ch];
                const float ib = s_v[256 + ch],  fb = s_v[320 + ch];
                const float c  = fmaf(fG, ct, iG * zG);
                const float cb = fmaf(fb, cbar, ib * zG);
                const float cd = fmaf(c - cb, e, cb);
                const float bef = oG * tanh_mufu(cd);
                ct = cd; cbar = cb;
                s_h[ch] = bef;
                BAR2_ARRIVE();          // release producers immediately

                g_state[(b * LP1 + l + 1) * HID + ch] = make_float4(c, cb, oG, dec);
                BAR3_SYNC();            // orders ALL epi STGs (sites <= l+1)
                if (ch == 0 && ((l + 1) & 63) == 0)
                    st_release_u32(&g_flag[b], (unsigned)((l + 1) >> 6));
            }
            if (ch == 0)
                st_release_u32(&g_flag[b], 1u << 20);
        }
    } else {
        // ===================== MC CONSUMER role (8 warps) ==================
        const int b   = blockIdx.x - BATCH;
        const int len = lens[b];
        const float bfv = bf[0];
        const float* sp = seq + b * MAXL;
        const float wf0 = Wf[lane], wf1 = Wf[lane + 32];
        float4* stg = smem.mc.stg[w];

        float acc = 0.0f;               // lane 0 per warp

        for (int k = 0; 64 * k <= len; k++) {
            if (j == 0) {
                while (ld_acquire_u32(&g_flag[b]) < (unsigned)(k + 1))
                    __nanosleep(256);
            }
            __syncthreads();

            const int sLim = min(64 * k + 63, len);
            for (int s = 64 * k + w; s <= sLim; s += 8) {
                float dtl;
                if (s < len) dtl = (s == 0) ? sp[0] : sp[s] - sp[s - 1];
                else         dtl = T_END - sp[len - 1];

                const int base = (b * LP1 + s) * HID;
                const float4 s0 = g_state[base + lane];
                const float4 s1 = g_state[base + lane + 32];
                const float mscale = -dtl * LOG2E;
                stg[lane]      = make_float4(s0.w * mscale, s0.x - s0.y, s0.y, s0.z * wf0);
                stg[lane + 32] = make_float4(s1.w * mscale, s1.x - s1.y, s1.y, s1.z * wf1);
                __syncwarp();

                float u = 1.0f;         // lanes 30,31: u=1 (lane30 dot = before.Wf)
                if (lane < NMC)
                    u = tf_uniform((uint32_t)lane * (uint32_t)TOTAL
                                   + (uint32_t)(b * LP1 + s));
                float a0 = 0.0f, a1 = 0.0f;
#pragma unroll 8
                for (int ch = 0; ch < HID; ch += 2) {
                    const float4 t0 = stg[ch], t1 = stg[ch + 1];
                    a0 = fmaf(t0.w, tanh_mufu(fmaf(t0.y, ex2f(u * t0.x), t0.z)), a0);
                    a1 = fmaf(t1.w, tanh_mufu(fmaf(t1.y, ex2f(u * t1.x), t1.z)), a1);
                }
                const float dot = a0 + a1;

                float spv = (lane < NMC) ? fsoftplus(dot + bfv) : 0.0f;
#pragma unroll
                for (int off = 16; off; off >>= 1)
                    spv += __shfl_xor_sync(0xFFFFFFFFu, spv, off);
                const float q = __shfl_sync(0xFFFFFFFFu, dot, 30);

                if (lane == 0) {
                    const float lamb_int = (spv * (1.0f / NMC) + EPS_L) * dtl;
                    float ev = 0.0f;
                    if (s < len) ev = flog(fsoftplus(q + bfv) + EPS_L);
                    acc += ev - lamb_int;
                }
                __syncwarp();
            }
        }

        if (lane == 0) smem.mc.red[w] = acc;
        __syncthreads();
        if (j == 0) {
            float S = 0.0f;
#pragma unroll
            for (int k = 0; k < 8; k++) S += smem.mc.red[k];
            g_part[b] = S;
            __threadfence();
            if (atomicAdd(&g_done, 1u) == (unsigned)(BATCH - 1)) {
                float T = 0.0f;
#pragma unroll 8
                for (int k = 0; k < BATCH; k++) T += g_part[k];
                out[0] = -T * (1.0f / BATCH);
                for (int k = 0; k < BATCH; k++) g_flag[k] = 0u;
                g_done = 0u;
            }
        }
    }
}

// ------------------------------- launcher ------------------------------------
extern "C" void kernel_launch(void* const* d_in, const int* in_sizes, int n_in,
                              void* d_out, int out_size)
{
    const float* seq  = nullptr;
    const float* Wrec = nullptr;
    const float* brec = nullptr;
    const float* Wf   = nullptr;
    const float* bf   = nullptr;
    const int*   lens = nullptr;
    for (int i = 0; i < n_in; i++) {
        const int s = in_sizes[i];
        if      (s == BATCH * MAXL)     seq  = (const float*)d_in[i];
        else if (s == 65 * NCOL)        Wrec = (const float*)d_in[i];
        else if (s == NCOL)             brec = (const float*)d_in[i];
        else if (s == 1)                bf   = (const float*)d_in[i];
        else if (s == HID) {
            if (!Wf) Wf = (const float*)d_in[i];
            else     lens = (const int*)d_in[i];
        }
    }

    hawkes_kernel<<<2 * BATCH, NTHR>>>(seq, Wrec, brec, Wf, bf, lens, (float*)d_out);
}

// round 17
// speedup vs baseline: 1.0532x; 1.0532x over previous
#include <cuda_runtime.h>
#include <cstdint>

// ---------------------------------------------------------------------------
// LSTM Neural Hawkes Process NLL  (B=64, L=1024, H=64)
// R17: R15 (best, 385us) + FUSED dual-column dot: both columns' 64-term dots
// share ONE set of h loads (8 LDS.128 instead of 16) with 4 interleaved
// fma2 accumulator chains. Identical arithmetic per column (same pair order).
// Everything else byte-identical to R15's passing kernel.
// ---------------------------------------------------------------------------

#define BATCH   64
#define MAXL    1024
#define LP1     1025
#define HID     64
#define NCOL    448
#define NTHR    224
#define NMC     30
#define T_END   100.0f
#define EPS_L   1e-10f
#define TOTAL   (BATCH * LP1)          // 65600
#define LOG2E   1.4426950408889634f
#define LN2     0.6931471805599453f

// ------------------------- device scratch (no mallocs) ---------------------
__device__ float4   g_state[TOTAL * HID];  // {c, cbar, o, dec}
__device__ unsigned g_flag [BATCH];
__device__ float    g_part [BATCH];
__device__ unsigned g_done = 0;

// ------------------------------ fast math -----------------------------------
__device__ __forceinline__ float ex2f(float x){ float y; asm("ex2.approx.f32 %0,%1;":"=f"(y):"f"(x)); return y; }
__device__ __forceinline__ float lg2f(float x){ float y; asm("lg2.approx.f32 %0,%1;":"=f"(y):"f"(x)); return y; }
__device__ __forceinline__ float tanh_mufu(float x){ float y; asm("tanh.approx.f32 %0,%1;":"=f"(y):"f"(x)); return y; }
__device__ __forceinline__ float fsoftplus(float x){
    return fmaxf(x, 0.0f) + LN2 * lg2f(1.0f + ex2f(-fabsf(x) * LOG2E));
}
__device__ __forceinline__ float flog(float x){ return LN2 * lg2f(x); }

// ------------------------------ packed f32x2 --------------------------------
__device__ __forceinline__ void fma2(unsigned long long& d, unsigned long long a, unsigned long long b){
    asm("fma.rn.f32x2 %0, %1, %2, %0;" : "+l"(d) : "l"(a), "l"(b));
}
__device__ __forceinline__ void add2(unsigned long long& d, unsigned long long a){
    asm("add.rn.f32x2 %0, %1, %0;" : "+l"(d) : "l"(a));
}
__device__ __forceinline__ unsigned long long pack2(float lo, float hi){
    unsigned long long r; asm("mov.b64 %0, {%1,%2};" : "=l"(r) : "f"(lo), "f"(hi)); return r;
}
__device__ __forceinline__ float2 unpack2(unsigned long long v){
    float2 r; asm("mov.b64 {%0,%1}, %2;" : "=f"(r.x), "=f"(r.y) : "l"(v)); return r;
}

// --------------------------- publish primitives ------------------------------
__device__ __forceinline__ void st_release_u32(unsigned* p, unsigned v){
    asm volatile("st.release.gpu.global.u32 [%0], %1;" :: "l"(p), "r"(v) : "memory");
}
__device__ __forceinline__ unsigned ld_acquire_u32(const unsigned* p){
    unsigned v;
    asm volatile("ld.acquire.gpu.global.u32 %0, [%1];" : "=r"(v) : "l"(p) : "memory");
    return v;
}

// ------------------------------ named barriers ------------------------------
#define BAR1_ARRIVE() asm volatile("bar.arrive 1, 224;" ::: "memory")
#define BAR1_SYNC()   asm volatile("bar.sync   1, 224;" ::: "memory")
#define BAR2_ARRIVE() asm volatile("bar.arrive 2, 224;" ::: "memory")
#define BAR2_SYNC()   asm volatile("bar.sync   2, 224;" ::: "memory")
#define BAR3_SYNC()   asm volatile("bar.sync   3, 64;"  ::: "memory")

// ------------------------------ Threefry-2x32-20 ----------------------------
__device__ __forceinline__ uint32_t rotl32(uint32_t x, int r){ return (x << r) | (x >> (32 - r)); }
__device__ __forceinline__ float tf_uniform(uint32_t flat){
    // JAX partitionable threefry, key (0,42): bits = out0 ^ out1
    uint32_t k0 = 0u, k1 = 42u, ks2 = k0 ^ k1 ^ 0x1BD11BDAu;
    uint32_t x0 = 0u + k0, x1 = flat + k1;
#define TF_R(r) { x0 += x1; x1 = rotl32(x1, (r)); x1 ^= x0; }
    TF_R(13) TF_R(15) TF_R(26) TF_R(6)   x0 += k1;  x1 += ks2 + 1u;
    TF_R(17) TF_R(29) TF_R(16) TF_R(24)  x0 += ks2; x1 += k0  + 2u;
    TF_R(13) TF_R(15) TF_R(26) TF_R(6)   x0 += k0;  x1 += k1  + 3u;
    TF_R(17) TF_R(29) TF_R(16) TF_R(24)  x0 += k1;  x1 += ks2 + 4u;
    TF_R(13) TF_R(15) TF_R(26) TF_R(6)   x0 += ks2; x1 += k0  + 5u;
#undef TF_R
    uint32_t bits = x0 ^ x1;
    return __uint_as_float((bits >> 9) | 0x3F800000u) - 1.0f;
}

// FUSED dual-column dot: one pass over h (8 LDS.128), 4 fma2 chains.
// Per-column accumulator pairing/order identical to the R15 col_dot.
__device__ __forceinline__ void dual_dot(const float* sh,
                                         const unsigned long long* wa,
                                         const unsigned long long* wb,
                                         float base0, float base1,
                                         float& r0, float& r1)
{
    unsigned long long a0 = 0ull, a1 = 0ull, b0 = 0ull, b1 = 0ull;
    const ulonglong2* h2 = reinterpret_cast<const ulonglong2*>(sh);
#pragma unroll
    for (int q = 0; q < 8; q++) {
        ulonglong2 u = h2[q], v = h2[q + 8];
        fma2(a0, wa[2*q],      u.x);
        fma2(a1, wa[2*q + 1],  u.y);
        fma2(b0, wb[2*q],      u.x);
        fma2(b1, wb[2*q + 1],  u.y);
        fma2(a0, wa[2*q + 16], v.x);
        fma2(a1, wa[2*q + 17], v.y);
        fma2(b0, wb[2*q + 16], v.x);
        fma2(b1, wb[2*q + 17], v.y);
    }
    add2(a0, a1); add2(b0, b1);
    float2 ra = unpack2(a0), rb = unpack2(b0);
    r0 = (ra.x + ra.y) + base0;
    r1 = (rb.x + rb.y) + base1;
}

// --------------------------- shared memory union -----------------------------
union SmemU {
    struct {
        float h[HID];
        float v[384];
        float dt[LP1];
    } scan;
    struct {
        float4 stg[7][HID];
        float  red[7];
    } mc;
};

// ------------------------------- main kernel ---------------------------------
__global__ void __launch_bounds__(NTHR, 1)
hawkes_kernel(const float* __restrict__ seq,    // [B, L, 1]
              const float* __restrict__ Wrec,   // [65, 448]
              const float* __restrict__ brec,   // [448]
              const float* __restrict__ Wf,     // [64]
              const float* __restrict__ bf,     // [1]
              const int*   __restrict__ lens,   // [B]
              float*       __restrict__ out)
{
    __shared__ SmemU smem;

    const int j    = threadIdx.x;
    const int w    = j >> 5;
    const int lane = j & 31;

    if (blockIdx.x < BATCH) {
        // ========================= SCAN role ===============================
        const int b   = blockIdx.x;
        const int len = lens[b];
        const float* sp = seq + b * MAXL;
        float* s_h  = smem.scan.h;
        float* s_v  = smem.scan.v;
        float* s_dt = smem.scan.dt;

        for (int l = j; l <= MAXL; l += NTHR) {
            float v;
            if (l < len)        v = (l == 0) ? sp[0] : sp[l] - sp[l - 1];
            else if (l == len)  v = T_END - sp[len - 1];
            else                v = -1.0f;
            s_dt[l] = v;
        }

        const int c0 = j;               // first column
        const int c1 = j + NTHR;        // second column
        const bool epi = (j >= 160);    // c1 in gate 6 -> epilogue thread
        const int ch  = j - 160;        // epilogue channel

        if (epi) {
            s_h[ch] = 0.0f;
            g_state[(b * LP1) * HID + ch] = make_float4(0.f, 0.f, 0.f, 0.f);
        }

        // weights for both columns
        const float w00 = Wrec[c0], bj0 = brec[c0];
        const float w01 = Wrec[c1], bj1 = brec[c1];
        unsigned long long w2a[32], w2b[32];
#pragma unroll
        for (int k = 0; k < 32; k++) {
            w2a[k] = pack2(Wrec[(2*k + 1) * NCOL + c0], Wrec[(2*k + 2) * NCOL + c0]);
            w2b[k] = pack2(Wrec[(2*k + 1) * NCOL + c1], Wrec[(2*k + 2) * NCOL + c1]);
        }

        // branchless nonlinearity constants (ga = 0.5 for sigmoid, 0 for tanh)
        const int g0 = c0 >> 6, g1 = c1 >> 6;
        const float al0 = (g0 == 2) ? 1.0f : 0.5f, be0 = al0;
        const float ga0 = (g0 == 2) ? 0.0f : 0.5f;
        const float al1 = (g1 == 2) ? 1.0f : 0.5f, be1 = al1;
        const float ga1 = (g1 == 2) ? 0.0f : 0.5f;

        __syncthreads();

        if (!epi) {
            // ----- producers: warps 0-4, fused dual-column dot -----
            for (int l = 0; l < len; l++) {
                const float dt = s_dt[l];
                float acc0, acc1;
                dual_dot(s_h, w2a, w2b,
                         fmaf(w00, dt, bj0), fmaf(w01, dt, bj1), acc0, acc1);
                s_v[c0] = fmaf(al0, tanh_mufu(be0 * acc0), ga0);
                s_v[c1] = fmaf(al1, tanh_mufu(be1 * acc1), ga1);
                BAR1_ARRIVE();
                BAR2_SYNC();            // h(l+1) ready
            }
        } else {
            // ----- epilogue: warps 5-6 (c1 = gate-6 column of channel ch) --
            float ct = 0.0f, cbar = 0.0f;
            for (int l = 0; l < len; l++) {
                const float dt = s_dt[l];
                float acc0, acc1;
                dual_dot(s_h, w2a, w2b,
                         fmaf(w00, dt, bj0), fmaf(w01, dt, bj1), acc0, acc1);
                s_v[c0] = fmaf(al0, tanh_mufu(be0 * acc0), ga0);
                const float dec = fsoftplus(acc1);
                const float e   = ex2f(-dec * s_dt[l + 1] * LOG2E);

                BAR1_SYNC();            // gates ready
                const float iG = s_v[ch],        fG = s_v[ 64 + ch];
                const float zG = s_v[128 + ch],  oG = s_v[192 + ch];
                const float ib = s_v[256 + ch],  fb = s_v[320 + ch];
                const float c  = fmaf(fG, ct, iG * zG);
                const float cb = fmaf(fb, cbar, ib * zG);
                const float cd = fmaf(c - cb, e, cb);
                const float bef = oG * tanh_mufu(cd);
                ct = cd; cbar = cb;
                s_h[ch] = bef;
                BAR2_ARRIVE();          // release producers immediately

                g_state[(b * LP1 + l + 1) * HID + ch] = make_float4(c, cb, oG, dec);
                BAR3_SYNC();            // orders ALL epi STGs (sites <= l+1)
                if (ch == 0 && ((l + 1) & 63) == 0)
                    st_release_u32(&g_flag[b], (unsigned)((l + 1) >> 6));
            }
            if (ch == 0)
                st_release_u32(&g_flag[b], 1u << 20);
        }
    } else {
        // ===================== MC CONSUMER role (7 warps) ==================
        const int b   = blockIdx.x - BATCH;
        const int len = lens[b];
        const float bfv = bf[0];
        const float* sp = seq + b * MAXL;
        const float wf0 = Wf[lane], wf1 = Wf[lane + 32];
        float4* stg = smem.mc.stg[w];

        float acc = 0.0f;               // lane 0 per warp

        for (int k = 0; 64 * k <= len; k++) {
            if (j == 0) {
                while (ld_acquire_u32(&g_flag[b]) < (unsigned)(k + 1))
                    __nanosleep(256);
            }
            __syncthreads();

            const int sLim = min(64 * k + 63, len);
            for (int s = 64 * k + w; s <= sLim; s += 7) {
                float dtl;
                if (s < len) dtl = (s == 0) ? sp[0] : sp[s] - sp[s - 1];
                else         dtl = T_END - sp[len - 1];

                const int base = (b * LP1 + s) * HID;
                const float4 s0 = g_state[base + lane];
                const float4 s1 = g_state[base + lane + 32];
                const float mscale = -dtl * LOG2E;
                stg[lane]      = make_float4(s0.w * mscale, s0.x - s0.y, s0.y, s0.z * wf0);
                stg[lane + 32] = make_float4(s1.w * mscale, s1.x - s1.y, s1.y, s1.z * wf1);
                __syncwarp();

                float u = 1.0f;         // lanes 30,31: u=1 (lane30 dot = before.Wf)
                if (lane < NMC)
                    u = tf_uniform((uint32_t)lane * (uint32_t)TOTAL
                                   + (uint32_t)(b * LP1 + s));
                float a0 = 0.0f, a1 = 0.0f;
#pragma unroll 8
                for (int ch = 0; ch < HID; ch += 2) {
                    const float4 t0 = stg[ch], t1 = stg[ch + 1];
                    a0 = fmaf(t0.w, tanh_mufu(fmaf(t0.y, ex2f(u * t0.x), t0.z)), a0);
                    a1 = fmaf(t1.w, tanh_mufu(fmaf(t1.y, ex2f(u * t1.x), t1.z)), a1);
                }
                const float dot = a0 + a1;

                float spv = (lane < NMC) ? fsoftplus(dot + bfv) : 0.0f;
#pragma unroll
                for (int off = 16; off; off >>= 1)
                    spv += __shfl_xor_sync(0xFFFFFFFFu, spv, off);
                const float q = __shfl_sync(0xFFFFFFFFu, dot, 30);

                if (lane == 0) {
                    const float lamb_int = (spv * (1.0f / NMC) + EPS_L) * dtl;
                    float ev = 0.0f;
                    if (s < len) ev = flog(fsoftplus(q + bfv) + EPS_L);
                    acc += ev - lamb_int;
                }
                __syncwarp();
            }
        }

        if (lane == 0) smem.mc.red[w] = acc;
        __syncthreads();
        if (j == 0) {
            float S = 0.0f;
#pragma unroll
            for (int k = 0; k < 7; k++) S += smem.mc.red[k];
            g_part[b] = S;
            __threadfence();
            if (atomicAdd(&g_done, 1u) == (unsigned)(BATCH - 1)) {
                float T = 0.0f;
#pragma unroll 8
                for (int k = 0; k < BATCH; k++) T += g_part[k];
                out[0] = -T * (1.0f / BATCH);
                for (int k = 0; k < BATCH; k++) g_flag[k] = 0u;
                g_done = 0u;
            }
        }
    }
}

// ------------------------------- launcher ------------------------------------
extern "C" void kernel_launch(void* const* d_in, const int* in_sizes, int n_in,
                              void* d_out, int out_size)
{
    const float* seq  = nullptr;
    const float* Wrec = nullptr;
    const float* brec = nullptr;
    const float* Wf   = nullptr;
    const float* bf   = nullptr;
    const int*   lens = nullptr;
    for (int i = 0; i < n_in; i++) {
        const int s = in_sizes[i];
        if      (s == BATCH * MAXL)     seq  = (const float*)d_in[i];
        else if (s == 65 * NCOL)        Wrec = (const float*)d_in[i];
        else if (s == NCOL)             brec = (const float*)d_in[i];
        else if (s == 1)                bf   = (const float*)d_in[i];
        else if (s == HID) {
            if (!Wf) Wf = (const float*)d_in[i];
            else     lens = (const int*)d_in[i];
        }
    }

    hawkes_kernel<<<2 * BATCH, NTHR>>>(seq, Wrec, brec, Wf, bf, lens, (float*)d_out);
}